// round 2
// baseline (speedup 1.0000x reference)
#include <cuda_runtime.h>
#include <cuda_bf16.h>

// Problem shape (fixed by the dataset)
#define BB   256
#define NN   8192
#define SD   14
#define NPTS (BB * NN)          // 2,097,152 points
#define TPB  256
#define NBLK (NPTS / TPB)       // 8192 blocks

// Accumulator component index:
// 0 = trans (k 0..5), 1 = rot (k 6..12), 2 = mass (k 13),
// 3 = phys, 4 = quat, 5 = massflow, 6 = bc
__device__ int    g_time_idx;
__device__ float  g_inv_dt[NN];       // precomputed 1/(dt+eps) per n
__device__ double g_part[NBLK * 7];   // per-block double partials (static scratch)

// ---------------------------------------------------------------------------
// Kernel 1: argmin_n |t[0,n]| (first index on tie) + build inv_dt table.
// ---------------------------------------------------------------------------
__global__ void pinn_prep_kernel(const float* __restrict__ t)
{
    __shared__ float svals[TPB];
    __shared__ int   sidx[TPB];
    const int tid = threadIdx.x;

    float best = 3.4e38f;
    int   bidx = 0;
    for (int n = tid; n < NN; n += TPB) {
        float v = fabsf(t[n]);
        if (v < best) { best = v; bidx = n; }   // strict < keeps earliest per-thread

        // finite-difference dt (forward / central / backward)
        float dt;
        if      (n == 0)      dt = t[1]      - t[0];
        else if (n == NN - 1) dt = t[NN - 1] - t[NN - 2];
        else                  dt = t[n + 1]  - t[n - 1];
        g_inv_dt[n] = 1.0f / (dt + 1e-12f);
    }
    svals[tid] = best; sidx[tid] = bidx;
    __syncthreads();
    for (int s = TPB / 2; s > 0; s >>= 1) {
        if (tid < s) {
            float v2 = svals[tid + s]; int i2 = sidx[tid + s];
            if (v2 < svals[tid] || (v2 == svals[tid] && i2 < sidx[tid])) {
                svals[tid] = v2; sidx[tid] = i2;
            }
        }
        __syncthreads();
    }
    if (tid == 0) g_time_idx = sidx[0];
}

// ---------------------------------------------------------------------------
// Kernel 2: main map-reduce. One thread per (b, n) point.
// ---------------------------------------------------------------------------
__global__ void __launch_bounds__(TPB)
pinn_main_kernel(const float* __restrict__ pred,
                 const float* __restrict__ tru,
                 const float* __restrict__ ctrl)
{
    const int i = blockIdx.x * TPB + threadIdx.x;  // 0 .. NPTS-1
    const int n = i & (NN - 1);                    // NN is a power of 2

    // Rows are 14 floats = 56 B; 56 % 8 == 0 -> float2-aligned everywhere.
    const float2* p2 = reinterpret_cast<const float2*>(pred);
    const float2* t2 = reinterpret_cast<const float2*>(tru);
    const int base = i * 7;
    const int pb   = base - ((n > 0)       ? 7 : 0);
    const int nb   = base + ((n < NN - 1)  ? 7 : 0);

    float cur[SD], prv[SD], nxt[SD];
#pragma unroll
    for (int k = 0; k < 7; k++) { float2 v = p2[base + k]; cur[2*k] = v.x; cur[2*k+1] = v.y; }
#pragma unroll
    for (int k = 0; k < 7; k++) { float2 v = p2[pb   + k]; prv[2*k] = v.x; prv[2*k+1] = v.y; }
#pragma unroll
    for (int k = 0; k < 7; k++) { float2 v = p2[nb   + k]; nxt[2*k] = v.x; nxt[2*k+1] = v.y; }

    // ---- data loss (COMP_W == 1 everywhere) ----
    float dsq[SD];
#pragma unroll
    for (int k = 0; k < 7; k++) {
        float2 v = t2[base + k];
        float d0 = cur[2*k]   - v.x;
        float d1 = cur[2*k+1] - v.y;
        dsq[2*k] = d0 * d0; dsq[2*k+1] = d1 * d1;
    }
    float s_tr = 0.f, s_rot = 0.f;
#pragma unroll
    for (int k = 0; k < 6; k++)  s_tr  += dsq[k];
#pragma unroll
    for (int k = 6; k < 13; k++) s_rot += dsq[k];
    float s_ms = dsq[13];
    float s_bc = (n == g_time_idx) ? (s_tr + s_rot + s_ms) : 0.f;

    const float inv_dt = g_inv_dt[n];

    // ---- dynamics ----
    const float vx = cur[3], vy = cur[4], vz = cur[5];
    const float q0 = cur[6], q1 = cur[7], q2 = cur[8], q3 = cur[9];
    const float wx = cur[10], wy = cur[11], wz = cur[12];
    const float m  = cur[13];
    const float4 u = reinterpret_cast<const float4*>(ctrl)[i];  // 16B-aligned

    const float thrust = u.x * 1.0e6f;
    const float bz0 = 2.0f * (q1 * q3 + q0 * q2);
    const float bz1 = 2.0f * (q2 * q3 - q0 * q1);
    const float bz2 = 1.0f - 2.0f * (q1 * q1 + q2 * q2);
    const float speed = sqrtf(vx * vx + vy * vy + vz * vz + 1e-12f);
    const float dc    = -0.30625f * speed;     // -0.5 * rho * Cd * A * speed
    const float invm  = 1.0f / m;

    float dyn[SD];
    dyn[0] = vx; dyn[1] = vy; dyn[2] = vz;
    dyn[3] = (thrust * bz0 + dc * vx) * invm;
    dyn[4] = (thrust * bz1 + dc * vy) * invm;
    dyn[5] = (thrust * bz2 + dc * vz) * invm - 9.80665f;
    dyn[6] = 0.5f * (-q1 * wx - q2 * wy - q3 * wz);
    dyn[7] = 0.5f * ( q0 * wx + q2 * wz - q3 * wy);
    dyn[8] = 0.5f * ( q0 * wy - q1 * wz + q3 * wx);
    dyn[9] = 0.5f * ( q0 * wz + q1 * wy - q2 * wx);
    dyn[10] = (u.y * 1.0e4f + 4000.0f * wy * wz) * (1.0f / 5000.0f);  // -(Izz-Iyy)=+4000
    dyn[11] = (u.z * 1.0e4f - 4000.0f * wz * wx) * (1.0f / 5000.0f);  // -(Ixx-Izz)=-4000
    dyn[12] =  u.w * 1.0e4f * (1.0f / 1000.0f);                       // (Iyy-Ixx)=0
    dyn[13] = -thrust * (1.0f / 2941.995f);                           // Isp*g0

    // ---- physics residual (boundary-safe: prv/nxt collapse to cur at ends) ----
    float s_ph = 0.f;
#pragma unroll
    for (int k = 0; k < SD; k++) {
        float r = (nxt[k] - prv[k]) * inv_dt - dyn[k];
        s_ph += r * r;
    }

    // ---- quaternion norm loss ----
    const float qn = sqrtf(q0 * q0 + q1 * q1 + q2 * q2 + q3 * q3);
    const float dq = qn - 1.0f;
    const float s_q = dq * dq;

    // ---- mass-flow loss: relu(mass[n+1]-mass[n]); exactly 0 at n==NN-1 ----
    const float s_mf = fmaxf(nxt[13] - cur[13], 0.0f);

    // ---- block reduction: warp shuffle (f32) -> shared -> double partial ----
    __shared__ float wsum[TPB / 32][7];
    float vals[7] = { s_tr, s_rot, s_ms, s_ph, s_q, s_mf, s_bc };
#pragma unroll
    for (int c = 0; c < 7; c++) {
        float v = vals[c];
#pragma unroll
        for (int o = 16; o > 0; o >>= 1) v += __shfl_down_sync(0xffffffffu, v, o);
        if ((threadIdx.x & 31) == 0) wsum[threadIdx.x >> 5][c] = v;
    }
    __syncthreads();
    if (threadIdx.x < 7) {
        double s = 0.0;
#pragma unroll
        for (int w = 0; w < TPB / 32; w++) s += (double)wsum[w][threadIdx.x];
        g_part[blockIdx.x * 7 + threadIdx.x] = s;   // plain store: deterministic
    }
}

// ---------------------------------------------------------------------------
// Kernel 3: deterministic final reduction over NBLK partials + finalize math.
// ---------------------------------------------------------------------------
__global__ void pinn_reduce_kernel(float* __restrict__ out)
{
    __shared__ double sh[TPB];
    double acc[7];
#pragma unroll
    for (int c = 0; c < 7; c++) acc[c] = 0.0;
    for (int b = threadIdx.x; b < NBLK; b += TPB) {
#pragma unroll
        for (int c = 0; c < 7; c++) acc[c] += g_part[b * 7 + c];
    }
    double tot[7];
#pragma unroll
    for (int c = 0; c < 7; c++) {
        sh[threadIdx.x] = acc[c];
        __syncthreads();
        for (int s = TPB / 2; s > 0; s >>= 1) {
            if (threadIdx.x < s) sh[threadIdx.x] += sh[threadIdx.x + s];
            __syncthreads();
        }
        tot[c] = sh[0];
        __syncthreads();
    }
    if (threadIdx.x == 0) {
        const double BN = (double)BB * (double)NN;
        double L_data = tot[0] / (BN * 6.0) + tot[1] / (BN * 7.0) + tot[2] / BN;
        double L_phys = tot[3] / (BN * 14.0);
        double L_quat = tot[4] / BN;
        double L_mf   = tot[5] / ((double)BB * (double)(NN - 1));
        double L_bc   = tot[6] / ((double)BB * 14.0);
        double total  = 1.0 * L_data + 0.1 * L_phys + 1.0 * L_bc
                      + 0.01 * L_quat + 0.01 * L_mf;
        out[0] = (float)total;
        out[1] = (float)L_data;
        out[2] = (float)L_phys;
        out[3] = (float)L_bc;
        out[4] = (float)L_quat;
        out[5] = (float)L_mf;
    }
}

// ---------------------------------------------------------------------------
extern "C" void kernel_launch(void* const* d_in, const int* in_sizes, int n_in,
                              void* d_out, int out_size)
{
    const float* pred = (const float*)d_in[0];   // (B, N, 14) f32
    const float* tru  = (const float*)d_in[1];   // (B, N, 14) f32
    const float* t    = (const float*)d_in[2];   // (B, N, 1)  f32 (broadcast over B)
    const float* ctrl = (const float*)d_in[3];   // (B, N, 4)  f32
    float* out        = (float*)d_out;           // 6 f32

    pinn_prep_kernel<<<1, TPB>>>(t);
    pinn_main_kernel<<<NBLK, TPB>>>(pred, tru, ctrl);
    pinn_reduce_kernel<<<1, TPB>>>(out);
}